// round 2
// baseline (speedup 1.0000x reference)
#include <cuda_runtime.h>
#include <stdint.h>

#define NUM_VERBS 117
#define NUM_HOIS  600
#define HOI_VEC   (NUM_HOIS / 4)      // 150 float4 per row
#define ROWS      8                   // batch rows per block
#define THREADS   256

__global__ __launch_bounds__(THREADS)
void scatter_verbs_kernel(const float* __restrict__ verb_scores,
                          const int*   __restrict__ map_words,   // raw 32-bit view of map buffer
                          float* __restrict__ out,
                          int batch)
{
    __shared__ int   s_map[NUM_HOIS];
    __shared__ float s_vs[ROWS][NUM_VERBS + 1];   // +1 pad
    __shared__ int   s_is_i32;                    // 1 if any odd word nonzero -> int32 layout

    const int tid  = threadIdx.x;
    const int row0 = blockIdx.x * ROWS;
    const int nrow = min(ROWS, batch - row0);

    if (tid == 0) s_is_i32 = 0;
    __syncthreads();

    // Detect layout: int64 little-endian => all odd 32-bit words are 0.
    for (int i = tid; i < NUM_HOIS / 2; i += THREADS)
        if (map_words[2 * i + 1] != 0) s_is_i32 = 1;   // benign race, all write 1
    __syncthreads();

    const int is_i32 = s_is_i32;
    for (int i = tid; i < NUM_HOIS; i += THREADS)
        s_map[i] = is_i32 ? map_words[i] : map_words[2 * i];

    // Verb scores for these rows -> smem (contiguous nrow*117 floats).
    if (nrow == ROWS) {
        const float4* src4 = reinterpret_cast<const float4*>(
            verb_scores + (size_t)row0 * NUM_VERBS);
        for (int i = tid; i < (ROWS * NUM_VERBS) / 4; i += THREADS) {  // 234 float4
            float4 v = src4[i];
            int e = i * 4;
            s_vs[(e    ) / NUM_VERBS][(e    ) % NUM_VERBS] = v.x;
            s_vs[(e + 1) / NUM_VERBS][(e + 1) % NUM_VERBS] = v.y;
            s_vs[(e + 2) / NUM_VERBS][(e + 2) % NUM_VERBS] = v.z;
            s_vs[(e + 3) / NUM_VERBS][(e + 3) % NUM_VERBS] = v.w;
        }
    } else {
        const float* src = verb_scores + (size_t)row0 * NUM_VERBS;
        for (int i = tid; i < nrow * NUM_VERBS; i += THREADS)
            s_vs[i / NUM_VERBS][i % NUM_VERBS] = src[i];
    }
    __syncthreads();

    // Gather + coalesced float4 stores.
    float4* out4 = reinterpret_cast<float4*>(out + (size_t)row0 * NUM_HOIS);
    const int total = nrow * HOI_VEC;
    for (int i = tid; i < total; i += THREADS) {
        int r = i / HOI_VEC;
        int q = i - r * HOI_VEC;
        int h = q * 4;
        float4 v;
        v.x = s_vs[r][s_map[h    ]];
        v.y = s_vs[r][s_map[h + 1]];
        v.z = s_vs[r][s_map[h + 2]];
        v.w = s_vs[r][s_map[h + 3]];
        out4[r * HOI_VEC + q] = v;
    }
}

extern "C" void kernel_launch(void* const* d_in, const int* in_sizes, int n_in,
                              void* d_out, int out_size)
{
    const float* verb_scores = (const float*)d_in[0];
    const int*   map_words   = (const int*)d_in[1];   // int32 OR int64 viewed as words
    float*       out         = (float*)d_out;

    const int batch  = in_sizes[0] / NUM_VERBS;   // 131072
    const int blocks = (batch + ROWS - 1) / ROWS; // 16384

    scatter_verbs_kernel<<<blocks, THREADS>>>(verb_scores, map_words, out, batch);
}

// round 5
// speedup vs baseline: 1.1466x; 1.1466x over previous
#include <cuda_runtime.h>
#include <stdint.h>

#define NUM_VERBS 117
#define NUM_HOIS  600
#define HOI_VEC   150                 // float4 per row
#define ROWS      32                  // batch rows per block
#define THREADS   256                 // 8 warps; each warp -> 4 rows
#define NWARPS    8
#define VSTRIDE   120                 // padded smem row stride (floats)

__global__ __launch_bounds__(THREADS)
void scatter_verbs_kernel(const float* __restrict__ verb_scores,
                          const int*   __restrict__ map_words,  // int32 OR int64 viewed as words
                          float* __restrict__ out,
                          int batch)
{
    __shared__ float s_vs[ROWS][VSTRIDE];

    const int tid  = threadIdx.x;
    const int lane = tid & 31;
    const int wid  = tid >> 5;
    const int row0 = blockIdx.x * ROWS;
    const int nrow = min(ROWS, batch - row0);

    // ---- detect map dtype: int64 little-endian => odd 32-bit words are zero.
    bool is64 = true;
    #pragma unroll
    for (int j = 0; j < 8; j++)
        is64 &= (__ldg(map_words + 2 * j + 1) == 0);

    // ---- preload this lane's 20 map indices into registers (reused for all rows)
    int idx[5][4];
    #pragma unroll
    for (int k = 0; k < 5; k++) {
        int q = lane + 32 * k;              // float4 column index
        if (q < HOI_VEC) {
            int h = 4 * q;
            if (is64) {
                idx[k][0] = __ldg(map_words + 2 * (h + 0));
                idx[k][1] = __ldg(map_words + 2 * (h + 1));
                idx[k][2] = __ldg(map_words + 2 * (h + 2));
                idx[k][3] = __ldg(map_words + 2 * (h + 3));
            } else {
                int4 m = __ldg(reinterpret_cast<const int4*>(map_words) + q);
                idx[k][0] = m.x; idx[k][1] = m.y; idx[k][2] = m.z; idx[k][3] = m.w;
            }
        }
    }

    // ---- stage verb rows into smem (contiguous nrow*117 floats, float4 loads)
    if (nrow == ROWS) {
        const float4* src4 = reinterpret_cast<const float4*>(
            verb_scores + (size_t)row0 * NUM_VERBS);
        for (int i = tid; i < (ROWS * NUM_VERBS) / 4; i += THREADS) {  // 936 floats
            float4 v = src4[i];
            int e = i * 4;
            s_vs[(e    ) / NUM_VERBS][(e    ) % NUM_VERBS] = v.x;
            s_vs[(e + 1) / NUM_VERBS][(e + 1) % NUM_VERBS] = v.y;
            s_vs[(e + 2) / NUM_VERBS][(e + 2) % NUM_VERBS] = v.z;
            s_vs[(e + 3) / NUM_VERBS][(e + 3) % NUM_VERBS] = v.w;
        }
    } else {
        const float* src = verb_scores + (size_t)row0 * NUM_VERBS;
        for (int i = tid; i < nrow * NUM_VERBS; i += THREADS)
            s_vs[i / NUM_VERBS][i % NUM_VERBS] = src[i];
    }
    __syncthreads();

    // ---- gather + coalesced float4 streaming stores; warp w -> rows w, w+8, w+16, w+24
    float4* out4 = reinterpret_cast<float4*>(out + (size_t)row0 * NUM_HOIS);
    #pragma unroll
    for (int j = 0; j < 4; j++) {
        int r = wid + NWARPS * j;
        if (r < nrow) {
            const float* vrow = s_vs[r];
            float4* orow = out4 + (size_t)r * HOI_VEC;
            #pragma unroll
            for (int k = 0; k < 5; k++) {
                int q = lane + 32 * k;
                if (q < HOI_VEC) {
                    float4 v;
                    v.x = vrow[idx[k][0]];
                    v.y = vrow[idx[k][1]];
                    v.z = vrow[idx[k][2]];
                    v.w = vrow[idx[k][3]];
                    __stcs(orow + q, v);
                }
            }
        }
    }
}

extern "C" void kernel_launch(void* const* d_in, const int* in_sizes, int n_in,
                              void* d_out, int out_size)
{
    const float* verb_scores = (const float*)d_in[0];
    const int*   map_words   = (const int*)d_in[1];
    float*       out         = (float*)d_out;

    const int batch  = in_sizes[0] / NUM_VERBS;     // 131072
    const int blocks = (batch + ROWS - 1) / ROWS;   // 4096

    scatter_verbs_kernel<<<blocks, THREADS>>>(verb_scores, map_words, out, batch);
}